// round 12
// baseline (speedup 1.0000x reference)
#include <cuda_runtime.h>
#include <cuda_bf16.h>
#include <cuda_fp16.h>
#include <cstdint>
#include <cstddef>

// Problem dims
#define BSZ  32
#define SEQ  2048
#define IND  512
#define HID  256
#define MROWS (BSZ * SEQ)          // 65536
#define NLANE (BSZ * HID)          // 8192 per direction

// ---------------- scratch (device globals; no allocs allowed) ---------------
// packed element = (bf16_hi << 16) | bf16_lo ; value = hi + lo (~fp32 precise)
__device__ uint32_t g_Pp[MROWS * HID];            // fc output, packed
__device__ uint32_t g_Yp[2 * MROWS * HID];        // layer0 outputs, packed [ltr|rtl]
__device__ uint2    g_C0[MROWS * HID];            // layer0 recur input {x_packed, sigma_f32}
__device__ uint2    g_C1[2 * MROWS * HID];        // layer1 recur input
__device__ uint32_t g_W2p[2 * HID * HID];         // W2 packed (both layers)

__device__ __forceinline__ float tanh_fast(float x) {
    float y;
    asm("tanh.approx.f32 %0, %1;" : "=f"(y) : "f"(x));
    return y;
}

__device__ __forceinline__ uint32_t smem_u32(const void* p) {
    uint32_t a;
    asm("{ .reg .u64 t; cvta.to.shared.u64 t, %1; cvt.u32.u64 %0, t; }"
        : "=r"(a) : "l"(p));
    return a;
}

__device__ __forceinline__ uint32_t prmt(uint32_t a, uint32_t b, uint32_t sel) {
    uint32_t r;
    asm("prmt.b32 %0, %1, %2, %3;" : "=r"(r) : "r"(a), "r"(b), "r"(sel));
    return r;
}

__device__ __forceinline__ void split2(float a, float b, uint32_t& hi, uint32_t& lo) {
    __nv_bfloat16 ha = __float2bfloat16_rn(a);
    __nv_bfloat16 hb = __float2bfloat16_rn(b);
    float ra = a - __bfloat162float(ha);
    float rb = b - __bfloat162float(hb);
    __nv_bfloat162 hh; hh.x = ha; hh.y = hb;
    __nv_bfloat162 ll = __floats2bfloat162_rn(ra, rb);
    hi = *reinterpret_cast<uint32_t*>(&hh);
    lo = *reinterpret_cast<uint32_t*>(&ll);
}

__device__ __forceinline__ uint32_t pack_hl(float v) {
    __nv_bfloat16 hb = __float2bfloat16_rn(v);
    float r = v - __bfloat162float(hb);
    __nv_bfloat16 lb = __float2bfloat16_rn(r);
    return ((uint32_t)*reinterpret_cast<unsigned short*>(&hb) << 16)
         |  (uint32_t)*reinterpret_cast<unsigned short*>(&lb);
}

__device__ __forceinline__ float unpack_hl(uint32_t p) {
    float hi = __uint_as_float(p & 0xFFFF0000u);
    float lo = __uint_as_float(p << 16);
    return hi + lo;
}

__device__ __forceinline__ void mma16816(
    float c[4], uint32_t a0, uint32_t a1, uint32_t a2, uint32_t a3,
    uint32_t b0, uint32_t b1)
{
    asm volatile(
        "mma.sync.aligned.m16n8k16.row.col.f32.bf16.bf16.f32 "
        "{%0,%1,%2,%3}, {%4,%5,%6,%7}, {%8,%9}, {%0,%1,%2,%3};"
        : "+f"(c[0]), "+f"(c[1]), "+f"(c[2]), "+f"(c[3])
        : "r"(a0), "r"(a1), "r"(a2), "r"(a3), "r"(b0), "r"(b1));
}

#define LDSM_X4(r0, r1, r2, r3, addr) \
    asm volatile("ldmatrix.sync.aligned.m8n8.x4.shared.b16 {%0,%1,%2,%3}, [%4];" \
        : "=r"(r0), "=r"(r1), "=r"(r2), "=r"(r3) : "r"(addr))

#define SB 80          // smem row stride (64B data + 16B pad)
#define OPB 10240      // one operand plane (128 rows * SB)
#define BUFB 40960     // one buffer (4 planes)
#define SMEM_DB 81920  // two buffers

// ===========================================================================
// GEMM compute core: BM=128, BN=128, BK=32; 8 warps (4Mx2N), warp tile 32x64.
// ===========================================================================
__device__ __forceinline__ void gemm_compute(
    uint32_t uB, uint32_t aoff, uint32_t boff, int wm, int wn, float acc[2][8][4])
{
    const uint32_t uAh = uB, uAl = uB + OPB, uWh = uB + 2*OPB, uWl = uB + 3*OPB;
    #pragma unroll
    for (int pass = 0; pass < 3; pass++) {
        const uint32_t uAt = (pass == 1) ? uAl : uAh;
        const uint32_t uWt = (pass == 2) ? uWl : uWh;
        const uint32_t aBase = uAt + (uint32_t)(wm * SB) + aoff;
        const uint32_t bBase = uWt + (uint32_t)(wn * SB) + boff;
        #pragma unroll
        for (int ks = 0; ks < 2; ks++) {
            const uint32_t ko = ks * 32;
            uint32_t bfr[8][2];
            #pragma unroll
            for (int p = 0; p < 4; p++) {
                LDSM_X4(bfr[2*p][0], bfr[2*p][1], bfr[2*p+1][0], bfr[2*p+1][1],
                        bBase + (uint32_t)(p * 16 * SB) + ko);
            }
            #pragma unroll
            for (int mt = 0; mt < 2; mt++) {
                uint32_t a0, a1, a2, a3;
                LDSM_X4(a0, a1, a2, a3, aBase + (uint32_t)(mt * 16 * SB) + ko);
                #pragma unroll
                for (int nt = 0; nt < 8; nt++)
                    mma16816(acc[mt][nt], a0, a1, a2, a3, bfr[nt][0], bfr[nt][1]);
            }
        }
    }
}

// ---------------------------------------------------------------------------
// fc GEMM: fp32 inputs, split in loader, double-buffered, epilogue packs u32.
// ---------------------------------------------------------------------------
__global__ __launch_bounds__(256, 2) void gemm_fc(
    const float* __restrict__ A, const float* __restrict__ W,
    const float* __restrict__ bias, uint32_t* __restrict__ Cp)
{
    extern __shared__ __align__(16) char sm[];
    const int tid  = threadIdx.x;
    const int lane = tid & 31;
    const int warp = tid >> 5;
    const int wm = (warp & 3) * 32, wn = (warp >> 2) * 64;
    const int r = lane >> 2, q = lane & 3;
    const uint32_t uS = smem_u32(sm);
    const uint32_t aoff = (uint32_t)((lane & 15) * SB + ((lane >> 4) << 4));
    const uint32_t boff = (uint32_t)(((lane & 7) + (lane >> 4) * 8) * SB + ((lane & 8) << 1));

    const int bm  = blockIdx.x * 128;
    const int bnG = blockIdx.y * 128;
    const int K = IND;
    const int lrow = tid >> 3, lc4 = (tid & 7) * 4;   // i-th row = lrow + i*32

    float acc[2][8][4];
    #pragma unroll
    for (int mt = 0; mt < 2; mt++)
        #pragma unroll
        for (int nt = 0; nt < 8; nt++)
            #pragma unroll
            for (int e = 0; e < 4; e++) acc[mt][nt][e] = 0.f;

    // prologue: chunk 0 into buf 0
    {
        #pragma unroll
        for (int i = 0; i < 4; i++) {
            int row = lrow + i * 32;
            float4 va = *reinterpret_cast<const float4*>(&A[(size_t)(bm + row) * K + lc4]);
            float4 vw = *reinterpret_cast<const float4*>(&W[(size_t)(bnG + row) * K + lc4]);
            uint2 hi, lo;
            int off = row * SB + lc4 * 2;
            split2(va.x, va.y, hi.x, lo.x); split2(va.z, va.w, hi.y, lo.y);
            *reinterpret_cast<uint2*>(sm + off) = hi;
            *reinterpret_cast<uint2*>(sm + OPB + off) = lo;
            split2(vw.x, vw.y, hi.x, lo.x); split2(vw.z, vw.w, hi.y, lo.y);
            *reinterpret_cast<uint2*>(sm + 2*OPB + off) = hi;
            *reinterpret_cast<uint2*>(sm + 3*OPB + off) = lo;
        }
    }
    __syncthreads();

    const int nch = K >> 5;
    for (int c = 0; c < nch; c++) {
        const bool hn = (c + 1) < nch;
        float4 va[4];
        if (hn) {
            const int k0 = (c + 1) << 5;
            #pragma unroll
            for (int i = 0; i < 4; i++)
                va[i] = *reinterpret_cast<const float4*>(
                    &A[(size_t)(bm + lrow + i * 32) * K + k0 + lc4]);
        }
        gemm_compute(uS + (uint32_t)((c & 1) * BUFB), aoff, boff, wm, wn, acc);
        if (hn) {
            const int k0 = (c + 1) << 5;
            char* bufB = sm + ((c + 1) & 1) * BUFB;
            float4 vw[4];
            #pragma unroll
            for (int i = 0; i < 4; i++)
                vw[i] = *reinterpret_cast<const float4*>(
                    &W[(size_t)(bnG + lrow + i * 32) * K + k0 + lc4]);
            #pragma unroll
            for (int i = 0; i < 4; i++) {
                int row = lrow + i * 32;
                int off = row * SB + lc4 * 2;
                uint2 hi, lo;
                split2(va[i].x, va[i].y, hi.x, lo.x);
                split2(va[i].z, va[i].w, hi.y, lo.y);
                *reinterpret_cast<uint2*>(bufB + off) = hi;
                *reinterpret_cast<uint2*>(bufB + OPB + off) = lo;
            }
            #pragma unroll
            for (int i = 0; i < 4; i++) {
                int row = lrow + i * 32;
                int off = row * SB + lc4 * 2;
                uint2 hi, lo;
                split2(vw[i].x, vw[i].y, hi.x, lo.x);
                split2(vw[i].z, vw[i].w, hi.y, lo.y);
                *reinterpret_cast<uint2*>(bufB + 2*OPB + off) = hi;
                *reinterpret_cast<uint2*>(bufB + 3*OPB + off) = lo;
            }
        }
        __syncthreads();
    }

    #pragma unroll
    for (int mt = 0; mt < 2; mt++) {
        const int row = bm + wm + mt * 16 + r;
        #pragma unroll
        for (int nt = 0; nt < 8; nt++) {
            const int col = bnG + wn + nt * 8 + q * 2;
            float b0 = bias[col], b1 = bias[col + 1];
            uint2 p0, p1;
            p0.x = pack_hl(acc[mt][nt][0] + b0);
            p0.y = pack_hl(acc[mt][nt][1] + b1);
            p1.x = pack_hl(acc[mt][nt][2] + b0);
            p1.y = pack_hl(acc[mt][nt][3] + b1);
            *reinterpret_cast<uint2*>(&Cp[(size_t)row * 256 + col]) = p0;
            *reinterpret_cast<uint2*>(&Cp[(size_t)(row + 8) * 256 + col]) = p1;
        }
    }
}

// ---------------------------------------------------------------------------
// Gate GEMM: packed u32 inputs, double-buffered; epilogue emits combined
// uint2 {x_packed (reloaded from A source), sigma_fp32}.
// ---------------------------------------------------------------------------
__global__ __launch_bounds__(256, 2) void gemm_gate(
    const uint32_t* __restrict__ Ap, const uint32_t* __restrict__ Wp,
    const float* __restrict__ bias, uint2* __restrict__ C2)
{
    extern __shared__ __align__(16) char sm[];
    const int tid  = threadIdx.x;
    const int lane = tid & 31;
    const int warp = tid >> 5;
    const int wm = (warp & 3) * 32, wn = (warp >> 2) * 64;
    const int r = lane >> 2, q = lane & 3;
    const uint32_t uS = smem_u32(sm);
    const uint32_t aoff = (uint32_t)((lane & 15) * SB + ((lane >> 4) << 4));
    const uint32_t boff = (uint32_t)(((lane & 7) + (lane >> 4) * 8) * SB + ((lane & 8) << 1));

    const int bm  = blockIdx.x * 128;
    const int bnG = blockIdx.y * 128;
    const int K = HID;   // 256
    const int lrow = tid >> 3, lc4 = (tid & 7) * 4;

    float acc[2][8][4];
    #pragma unroll
    for (int mt = 0; mt < 2; mt++)
        #pragma unroll
        for (int nt = 0; nt < 8; nt++)
            #pragma unroll
            for (int e = 0; e < 4; e++) acc[mt][nt][e] = 0.f;

    // prologue: chunk 0 into buf 0
    {
        #pragma unroll
        for (int i = 0; i < 4; i++) {
            int row = lrow + i * 32;
            uint4 va = *reinterpret_cast<const uint4*>(&Ap[(size_t)(bm + row) * K + lc4]);
            uint4 vw = *reinterpret_cast<const uint4*>(&Wp[(size_t)(bnG + row) * K + lc4]);
            int off = row * SB + lc4 * 2;
            uint2 hi, lo;
            hi.x = prmt(va.x, va.y, 0x7632); lo.x = prmt(va.x, va.y, 0x5410);
            hi.y = prmt(va.z, va.w, 0x7632); lo.y = prmt(va.z, va.w, 0x5410);
            *reinterpret_cast<uint2*>(sm + off) = hi;
            *reinterpret_cast<uint2*>(sm + OPB + off) = lo;
            hi.x = prmt(vw.x, vw.y, 0x7632); lo.x = prmt(vw.x, vw.y, 0x5410);
            hi.y = prmt(vw.z, vw.w, 0x7632); lo.y = prmt(vw.z, vw.w, 0x5410);
            *reinterpret_cast<uint2*>(sm + 2*OPB + off) = hi;
            *reinterpret_cast<uint2*>(sm + 3*OPB + off) = lo;
        }
    }
    __syncthreads();

    const int nch = K >> 5;   // 8
    for (int c = 0; c < nch; c++) {
        const bool hn = (c + 1) < nch;
        uint4 va[4];
        if (hn) {
            const int k0 = (c + 1) << 5;
            #pragma unroll
            for (int i = 0; i < 4; i++)
                va[i] = *reinterpret_cast<const uint4*>(
                    &Ap[(size_t)(bm + lrow + i * 32) * K + k0 + lc4]);
        }
        gemm_compute(uS + (uint32_t)((c & 1) * BUFB), aoff, boff, wm, wn, acc);
        if (hn) {
            const int k0 = (c + 1) << 5;
            char* bufB = sm + ((c + 1) & 1) * BUFB;
            uint4 vw[4];
            #pragma unroll
            for (int i = 0; i < 4; i++)
                vw[i] = *reinterpret_cast<const uint4*>(
                    &Wp[(size_t)(bnG + lrow + i * 32) * K + k0 + lc4]);
            #pragma unroll
            for (int i = 0; i < 4; i++) {
                int row = lrow + i * 32;
                int off = row * SB + lc4 * 2;
                uint2 hi, lo;
                hi.x = prmt(va[i].x, va[i].y, 0x7632); lo.x = prmt(va[i].x, va[i].y, 0x5410);
                hi.y = prmt(va[i].z, va[i].w, 0x7632); lo.y = prmt(va[i].z, va[i].w, 0x5410);
                *reinterpret_cast<uint2*>(bufB + off) = hi;
                *reinterpret_cast<uint2*>(bufB + OPB + off) = lo;
            }
            #pragma unroll
            for (int i = 0; i < 4; i++) {
                int row = lrow + i * 32;
                int off = row * SB + lc4 * 2;
                uint2 hi, lo;
                hi.x = prmt(vw[i].x, vw[i].y, 0x7632); lo.x = prmt(vw[i].x, vw[i].y, 0x5410);
                hi.y = prmt(vw[i].z, vw[i].w, 0x7632); lo.y = prmt(vw[i].z, vw[i].w, 0x5410);
                *reinterpret_cast<uint2*>(bufB + 2*OPB + off) = hi;
                *reinterpret_cast<uint2*>(bufB + 3*OPB + off) = lo;
            }
        }
        __syncthreads();
    }

    // epilogue: sigma fp32 + x reload -> combined uint2 {x_packed, sigma}
    #pragma unroll
    for (int mt = 0; mt < 2; mt++) {
        const int row = bm + wm + mt * 16 + r;
        #pragma unroll
        for (int nt = 0; nt < 8; nt++) {
            const int col = bnG + wn + nt * 8 + q * 2;
            float b0 = bias[col], b1 = bias[col + 1];
            uint2 x0 = *reinterpret_cast<const uint2*>(&Ap[(size_t)row * 256 + col]);
            uint2 x1 = *reinterpret_cast<const uint2*>(&Ap[(size_t)(row + 8) * 256 + col]);
            float s00 = fmaf(tanh_fast(0.5f * (acc[mt][nt][0] + b0)), 0.5f, 0.5f);
            float s01 = fmaf(tanh_fast(0.5f * (acc[mt][nt][1] + b1)), 0.5f, 0.5f);
            float s10 = fmaf(tanh_fast(0.5f * (acc[mt][nt][2] + b0)), 0.5f, 0.5f);
            float s11 = fmaf(tanh_fast(0.5f * (acc[mt][nt][3] + b1)), 0.5f, 0.5f);
            uint4 o0, o1;
            o0.x = x0.x; o0.y = __float_as_uint(s00);
            o0.z = x0.y; o0.w = __float_as_uint(s01);
            o1.x = x1.x; o1.y = __float_as_uint(s10);
            o1.z = x1.y; o1.w = __float_as_uint(s11);
            *reinterpret_cast<uint4*>(&C2[(size_t)row * 256 + col]) = o0;
            *reinterpret_cast<uint4*>(&C2[(size_t)(row + 8) * 256 + col]) = o1;
        }
    }
}

// ---------------------------------------------------------------------------
__global__ __launch_bounds__(256) void prep_w(const float* __restrict__ W2,
                                              uint32_t* __restrict__ W2p)
{
    int i = blockIdx.x * blockDim.x + threadIdx.x;
    W2p[i] = pack_hl(W2[i]);
}

// ---------------------------------------------------------------------------
// Recurrence: single uint2 {x_packed, sigma_f32} stream; ring depth 32.
// POUT: write packed u32 (layer0) else fp32 (layer1 -> d_out).
// ---------------------------------------------------------------------------
#define PD 32

template <bool POUT>
__global__ __launch_bounds__(128) void recur2(
    const uint2* __restrict__ X0,
    uint32_t* __restrict__ P0, float* __restrict__ F0, int yld0, int yoff0,
    const uint2* __restrict__ X1,
    uint32_t* __restrict__ P1, float* __restrict__ F1, int yld1, int yoff1)
{
    const int dir = blockIdx.y;
    const uint2* __restrict__ X = dir ? X1 : X0;
    uint32_t* __restrict__ Yp = dir ? P1 : P0;
    float*    __restrict__ Yf = dir ? F1 : F0;
    const int yld  = dir ? yld1  : yld0;
    const int yoff = dir ? yoff1 : yoff0;

    const int gg = blockIdx.x * blockDim.x + threadIdx.x;
    const int b = gg >> 8;
    const int j = gg & 255;

    const int t0 = dir ? (SEQ - 1) : 0;
    const ptrdiff_t xstep = dir ? -(ptrdiff_t)HID : (ptrdiff_t)HID;
    const ptrdiff_t ystep = dir ? -(ptrdiff_t)yld : (ptrdiff_t)yld;

    const uint2* xp = X + ((size_t)b * SEQ + t0) * HID + j;
    const size_t ybase = (size_t)b * SEQ * yld + (size_t)t0 * yld + yoff + j;
    uint32_t* ypp = POUT ? (Yp + ybase) : nullptr;
    float*    ypf = POUT ? nullptr : (Yf + ybase);

    uint2 xr[PD];
    #pragma unroll
    for (int d = 0; d < PD; d++)
        xr[d] = xp[(ptrdiff_t)d * xstep];
    const uint2* xq = xp + (ptrdiff_t)PD * xstep;

    float h = 0.f;
    #pragma unroll 1
    for (int blk = 0; blk < SEQ / PD - 1; blk++) {
        #pragma unroll
        for (int d = 0; d < PD; d++) {
            float xv = unpack_hl(xr[d].x);
            float a  = __uint_as_float(xr[d].y);
            float c  = fmaf(-a, xv, xv);
            float t  = fmaf(a, h, c);
            h = tanh_fast(xv * t);
            if (POUT) { *ypp = pack_hl(h); ypp += ystep; }
            else      { *ypf = h;          ypf += ystep; }
            xr[d] = *xq;
            xq += xstep;
        }
    }
    #pragma unroll
    for (int d = 0; d < PD; d++) {
        float xv = unpack_hl(xr[d].x);
        float a  = __uint_as_float(xr[d].y);
        float c  = fmaf(-a, xv, xv);
        float t  = fmaf(a, h, c);
        h = tanh_fast(xv * t);
        if (POUT) { *ypp = pack_hl(h); ypp += ystep; }
        else      { *ypf = h;          ypf += ystep; }
    }
}

// ---------------------------------------------------------------------------
__global__ __launch_bounds__(256) void copy_hout(
    const uint32_t* __restrict__ Ypl, const uint32_t* __restrict__ Ypr,
    const float* __restrict__ xx, float* __restrict__ hout)
{
    int gg = blockIdx.x * blockDim.x + threadIdx.x;
    int j = gg & 255;
    int b = (gg >> 8) & 31;
    int s = gg >> 13;
    float v;
    if      (s == 0) v = unpack_hl(Ypl[((size_t)b * SEQ + (SEQ - 1)) * HID + j]);
    else if (s == 1) v = unpack_hl(Ypr[((size_t)b * SEQ) * HID + j]);
    else if (s == 2) v = xx[((size_t)b * SEQ + (SEQ - 1)) * (2 * HID) + j];
    else             v = xx[((size_t)b * SEQ) * (2 * HID) + HID + j];
    hout[gg] = v;
}

// ---------------------------------------------------------------------------
extern "C" void kernel_launch(void* const* d_in, const int* in_sizes, int n_in,
                              void* d_out, int out_size)
{
    const float* x    = (const float*)d_in[0];
    const float* W_fc = (const float*)d_in[1];
    const float* b_fc = (const float*)d_in[2];
    // d_in[3] = W1, d_in[4] = b1 : dead (g1*x + (1-g1)*x == x)
    const float* W2   = (const float*)d_in[5];
    const float* b2   = (const float*)d_in[6];
    float* out = (float*)d_out;

    uint32_t *Pp, *Yp, *W2p;
    uint2 *C0, *C1;
    cudaGetSymbolAddress((void**)&Pp,  g_Pp);
    cudaGetSymbolAddress((void**)&Yp,  g_Yp);
    cudaGetSymbolAddress((void**)&C0,  g_C0);
    cudaGetSymbolAddress((void**)&C1,  g_C1);
    cudaGetSymbolAddress((void**)&W2p, g_W2p);

    uint32_t* Ypl = Yp;
    uint32_t* Ypr = Yp + (size_t)MROWS * HID;
    float* hout = out + (size_t)BSZ * SEQ * 2 * HID;

    cudaFuncSetAttribute(gemm_fc,   cudaFuncAttributeMaxDynamicSharedMemorySize, SMEM_DB);
    cudaFuncSetAttribute(gemm_gate, cudaFuncAttributeMaxDynamicSharedMemorySize, SMEM_DB);

    // 0) pre-split W2 (both layers) into packed format
    prep_w<<<2 * HID * HID / 256, 256>>>(W2, W2p);

    // 1) fc projection -> packed P
    {
        dim3 grid(MROWS / 128, 2);
        gemm_fc<<<grid, 256, SMEM_DB>>>(x, W_fc, b_fc, Pp);
    }

    // 2) layer 0 gates (shared by both dirs) -> combined {x, sigma}
    {
        dim3 grid(MROWS / 128, 2);
        gemm_gate<<<grid, 256, SMEM_DB>>>(Pp, W2p, b2, C0);
    }

    // 3) layer 0 recurrence -> packed Y
    {
        dim3 grid(NLANE / 128, 2);
        recur2<true><<<grid, 128>>>(C0, Ypl, nullptr, HID, 0,
                                    C0, Ypr, nullptr, HID, 0);
    }

    // 4) layer 1 gates: one GEMM over [2*MROWS, 256] -> combined
    {
        dim3 grid(2 * MROWS / 128, 2);
        gemm_gate<<<grid, 256, SMEM_DB>>>(Yp, W2p + HID * HID, b2 + HID, C1);
    }

    // 5) layer 1 recurrence -> d_out fp32 (feature stride 512)
    {
        dim3 grid(NLANE / 128, 2);
        recur2<false><<<grid, 128>>>(C1, nullptr, out, 2 * HID, 0,
                                     C1 + (size_t)MROWS * HID, nullptr, out, 2 * HID, HID);
    }

    // 6) final hidden states
    copy_hout<<<BSZ * HID * 4 / 256, 256>>>(Ypl, Ypr, out, hout);
}

// round 13
// speedup vs baseline: 1.3481x; 1.3481x over previous
#include <cuda_runtime.h>
#include <cuda_bf16.h>
#include <cuda_fp16.h>
#include <cstdint>
#include <cstddef>

// Problem dims
#define BSZ  32
#define SEQ  2048
#define IND  512
#define HID  256
#define MROWS (BSZ * SEQ)          // 65536
#define NLANE (BSZ * HID)          // 8192 per direction

// ---------------- scratch (device globals; no allocs allowed) ---------------
// packed element = (bf16_hi << 16) | bf16_lo ; value = hi + lo (~fp32 precise)
__device__ uint32_t g_Pp[MROWS * HID];            // fc output, packed
__device__ uint32_t g_Yp[2 * MROWS * HID];        // layer0 outputs, packed [ltr|rtl]
__device__ uint2    g_C0[MROWS * HID];            // layer0 recur input {x_packed, sigma}
__device__ uint2    g_C1[2 * MROWS * HID];        // layer1 recur input
__device__ uint32_t g_W2p[2 * HID * HID];         // W2 packed (both layers)

__device__ __forceinline__ float tanh_fast(float x) {
    float y;
    asm("tanh.approx.f32 %0, %1;" : "=f"(y) : "f"(x));
    return y;
}

__device__ __forceinline__ uint32_t smem_u32(const void* p) {
    uint32_t a;
    asm("{ .reg .u64 t; cvta.to.shared.u64 t, %1; cvt.u32.u64 %0, t; }"
        : "=r"(a) : "l"(p));
    return a;
}

__device__ __forceinline__ uint32_t prmt(uint32_t a, uint32_t b, uint32_t sel) {
    uint32_t r;
    asm("prmt.b32 %0, %1, %2, %3;" : "=r"(r) : "r"(a), "r"(b), "r"(sel));
    return r;
}

__device__ __forceinline__ void split2(float a, float b, uint32_t& hi, uint32_t& lo) {
    __nv_bfloat16 ha = __float2bfloat16_rn(a);
    __nv_bfloat16 hb = __float2bfloat16_rn(b);
    float ra = a - __bfloat162float(ha);
    float rb = b - __bfloat162float(hb);
    __nv_bfloat162 hh; hh.x = ha; hh.y = hb;
    __nv_bfloat162 ll = __floats2bfloat162_rn(ra, rb);
    hi = *reinterpret_cast<uint32_t*>(&hh);
    lo = *reinterpret_cast<uint32_t*>(&ll);
}

__device__ __forceinline__ uint32_t pack_hl(float v) {
    __nv_bfloat16 hb = __float2bfloat16_rn(v);
    float r = v - __bfloat162float(hb);
    __nv_bfloat16 lb = __float2bfloat16_rn(r);
    return ((uint32_t)*reinterpret_cast<unsigned short*>(&hb) << 16)
         |  (uint32_t)*reinterpret_cast<unsigned short*>(&lb);
}

__device__ __forceinline__ float unpack_hl(uint32_t p) {
    float hi = __uint_as_float(p & 0xFFFF0000u);
    float lo = __uint_as_float(p << 16);
    return hi + lo;
}

__device__ __forceinline__ void mma16816(
    float c[4], uint32_t a0, uint32_t a1, uint32_t a2, uint32_t a3,
    uint32_t b0, uint32_t b1)
{
    asm volatile(
        "mma.sync.aligned.m16n8k16.row.col.f32.bf16.bf16.f32 "
        "{%0,%1,%2,%3}, {%4,%5,%6,%7}, {%8,%9}, {%0,%1,%2,%3};"
        : "+f"(c[0]), "+f"(c[1]), "+f"(c[2]), "+f"(c[3])
        : "r"(a0), "r"(a1), "r"(a2), "r"(a3), "r"(b0), "r"(b1));
}

#define LDSM_X4(r0, r1, r2, r3, addr) \
    asm volatile("ldmatrix.sync.aligned.m8n8.x4.shared.b16 {%0,%1,%2,%3}, [%4];" \
        : "=r"(r0), "=r"(r1), "=r"(r2), "=r"(r3) : "r"(addr))

#define SB 80   // smem row stride bytes (64B data + 16B pad)

// ===========================================================================
// GEMM compute core: BM=128, BN=128, BK=32; 8 warps (4Mx2N), warp tile 32x64.
// ===========================================================================
struct GemmCtx {
    uint32_t uAh, uAl, uWh, uWl;
    uint32_t aoff, boff;
    int wm, wn, r, q;
};

__device__ __forceinline__ void gemm_compute(
    const GemmCtx& g, float acc[2][8][4])
{
    #pragma unroll
    for (int pass = 0; pass < 3; pass++) {
        const uint32_t uAt = (pass == 1) ? g.uAl : g.uAh;
        const uint32_t uWt = (pass == 2) ? g.uWl : g.uWh;
        const uint32_t aBase = uAt + (uint32_t)(g.wm * SB) + g.aoff;
        const uint32_t bBase = uWt + (uint32_t)(g.wn * SB) + g.boff;
        #pragma unroll
        for (int ks = 0; ks < 2; ks++) {
            const uint32_t ko = ks * 32;
            uint32_t bfr[8][2];
            #pragma unroll
            for (int p = 0; p < 4; p++) {
                LDSM_X4(bfr[2*p][0], bfr[2*p][1], bfr[2*p+1][0], bfr[2*p+1][1],
                        bBase + (uint32_t)(p * 16 * SB) + ko);
            }
            #pragma unroll
            for (int mt = 0; mt < 2; mt++) {
                uint32_t a0, a1, a2, a3;
                LDSM_X4(a0, a1, a2, a3, aBase + (uint32_t)(mt * 16 * SB) + ko);
                #pragma unroll
                for (int nt = 0; nt < 8; nt++)
                    mma16816(acc[mt][nt], a0, a1, a2, a3, bfr[nt][0], bfr[nt][1]);
            }
        }
    }
}

// ---------------------------------------------------------------------------
// fc GEMM: fp32 inputs (x, W_fc), split in loader, epilogue packs to u32.
// K = 512. Single-buffered (no cross-compute register prefetch).
// ---------------------------------------------------------------------------
__global__ __launch_bounds__(256, 2) void gemm_fc(
    const float* __restrict__ A, const float* __restrict__ W,
    const float* __restrict__ bias, uint32_t* __restrict__ Cp)
{
    __shared__ __align__(16) char sAh[128 * SB];
    __shared__ __align__(16) char sAl[128 * SB];
    __shared__ __align__(16) char sWh[128 * SB];
    __shared__ __align__(16) char sWl[128 * SB];

    const int tid  = threadIdx.x;
    const int lane = tid & 31;
    const int warp = tid >> 5;
    GemmCtx g;
    g.wm = (warp & 3) * 32; g.wn = (warp >> 2) * 64;
    g.r = lane >> 2; g.q = lane & 3;
    g.uAh = smem_u32(sAh); g.uAl = smem_u32(sAl);
    g.uWh = smem_u32(sWh); g.uWl = smem_u32(sWl);
    g.aoff = (uint32_t)((lane & 15) * SB + ((lane >> 4) << 4));
    g.boff = (uint32_t)(((lane & 7) + (lane >> 4) * 8) * SB + ((lane & 8) << 1));

    const int bm  = blockIdx.x * 128;
    const int bnG = blockIdx.y * 128;
    const int K = IND;

    float acc[2][8][4];
    #pragma unroll
    for (int mt = 0; mt < 2; mt++)
        #pragma unroll
        for (int nt = 0; nt < 8; nt++)
            #pragma unroll
            for (int e = 0; e < 4; e++) acc[mt][nt][e] = 0.f;

    for (int c = 0; c < (K >> 5); c++) {
        const int k0 = c << 5;
        #pragma unroll
        for (int i = 0; i < 4; i++) {
            int idx = i * 256 + tid;
            int row = idx >> 3;
            int c4  = (idx & 7) * 4;
            float4 va = *reinterpret_cast<const float4*>(
                &A[(size_t)(bm + row) * K + k0 + c4]);
            float4 vw = *reinterpret_cast<const float4*>(
                &W[(size_t)(bnG + row) * K + k0 + c4]);
            uint2 ahi, alo, whi, wlo;
            split2(va.x, va.y, ahi.x, alo.x);
            split2(va.z, va.w, ahi.y, alo.y);
            split2(vw.x, vw.y, whi.x, wlo.x);
            split2(vw.z, vw.w, whi.y, wlo.y);
            int off = row * SB + c4 * 2;
            *reinterpret_cast<uint2*>(sAh + off) = ahi;
            *reinterpret_cast<uint2*>(sAl + off) = alo;
            *reinterpret_cast<uint2*>(sWh + off) = whi;
            *reinterpret_cast<uint2*>(sWl + off) = wlo;
        }
        __syncthreads();
        gemm_compute(g, acc);
        __syncthreads();
    }

    #pragma unroll
    for (int mt = 0; mt < 2; mt++) {
        const int row = bm + g.wm + mt * 16 + g.r;
        #pragma unroll
        for (int nt = 0; nt < 8; nt++) {
            const int col = bnG + g.wn + nt * 8 + g.q * 2;
            float b0 = bias[col], b1 = bias[col + 1];
            uint2 p0, p1;
            p0.x = pack_hl(acc[mt][nt][0] + b0);
            p0.y = pack_hl(acc[mt][nt][1] + b1);
            p1.x = pack_hl(acc[mt][nt][2] + b0);
            p1.y = pack_hl(acc[mt][nt][3] + b1);
            *reinterpret_cast<uint2*>(&Cp[(size_t)row * 256 + col]) = p0;
            *reinterpret_cast<uint2*>(&Cp[(size_t)(row + 8) * 256 + col]) = p1;
        }
    }
}

// ---------------------------------------------------------------------------
// Gate GEMM: packed u32 inputs (A, W pre-split), K=256, single-buffered.
// Loader = LDG + PRMT unpack. Epilogue: combined uint2 {x_packed, sigma_f32}.
// ---------------------------------------------------------------------------
__global__ __launch_bounds__(256, 2) void gemm_gate(
    const uint32_t* __restrict__ Ap, const uint32_t* __restrict__ Wp,
    const float* __restrict__ bias, uint2* __restrict__ C2)
{
    __shared__ __align__(16) char sAh[128 * SB];
    __shared__ __align__(16) char sAl[128 * SB];
    __shared__ __align__(16) char sWh[128 * SB];
    __shared__ __align__(16) char sWl[128 * SB];

    const int tid  = threadIdx.x;
    const int lane = tid & 31;
    const int warp = tid >> 5;
    GemmCtx g;
    g.wm = (warp & 3) * 32; g.wn = (warp >> 2) * 64;
    g.r = lane >> 2; g.q = lane & 3;
    g.uAh = smem_u32(sAh); g.uAl = smem_u32(sAl);
    g.uWh = smem_u32(sWh); g.uWl = smem_u32(sWl);
    g.aoff = (uint32_t)((lane & 15) * SB + ((lane >> 4) << 4));
    g.boff = (uint32_t)(((lane & 7) + (lane >> 4) * 8) * SB + ((lane & 8) << 1));

    const int bm  = blockIdx.x * 128;
    const int bnG = blockIdx.y * 128;
    const int K = HID;   // 256

    float acc[2][8][4];
    #pragma unroll
    for (int mt = 0; mt < 2; mt++)
        #pragma unroll
        for (int nt = 0; nt < 8; nt++)
            #pragma unroll
            for (int e = 0; e < 4; e++) acc[mt][nt][e] = 0.f;

    for (int c = 0; c < (K >> 5); c++) {
        const int k0 = c << 5;
        #pragma unroll
        for (int i = 0; i < 4; i++) {
            int idx = i * 256 + tid;
            int row = idx >> 3;
            int c4  = (idx & 7) * 4;
            uint4 va = *reinterpret_cast<const uint4*>(
                &Ap[(size_t)(bm + row) * K + k0 + c4]);
            uint4 vw = *reinterpret_cast<const uint4*>(
                &Wp[(size_t)(bnG + row) * K + k0 + c4]);
            uint2 ahi, alo, whi, wlo;
            ahi.x = prmt(va.x, va.y, 0x7632); alo.x = prmt(va.x, va.y, 0x5410);
            ahi.y = prmt(va.z, va.w, 0x7632); alo.y = prmt(va.z, va.w, 0x5410);
            whi.x = prmt(vw.x, vw.y, 0x7632); wlo.x = prmt(vw.x, vw.y, 0x5410);
            whi.y = prmt(vw.z, vw.w, 0x7632); wlo.y = prmt(vw.z, vw.w, 0x5410);
            int off = row * SB + c4 * 2;
            *reinterpret_cast<uint2*>(sAh + off) = ahi;
            *reinterpret_cast<uint2*>(sAl + off) = alo;
            *reinterpret_cast<uint2*>(sWh + off) = whi;
            *reinterpret_cast<uint2*>(sWl + off) = wlo;
        }
        __syncthreads();
        gemm_compute(g, acc);
        __syncthreads();
    }

    // epilogue: sigma fp32 + x reload -> combined uint2 {x_packed, sigma}
    #pragma unroll
    for (int mt = 0; mt < 2; mt++) {
        const int row = bm + g.wm + mt * 16 + g.r;
        #pragma unroll
        for (int nt = 0; nt < 8; nt++) {
            const int col = bnG + g.wn + nt * 8 + g.q * 2;
            float b0 = bias[col], b1 = bias[col + 1];
            uint2 x0 = *reinterpret_cast<const uint2*>(&Ap[(size_t)row * 256 + col]);
            uint2 x1 = *reinterpret_cast<const uint2*>(&Ap[(size_t)(row + 8) * 256 + col]);
            float s00 = fmaf(tanh_fast(0.5f * (acc[mt][nt][0] + b0)), 0.5f, 0.5f);
            float s01 = fmaf(tanh_fast(0.5f * (acc[mt][nt][1] + b1)), 0.5f, 0.5f);
            float s10 = fmaf(tanh_fast(0.5f * (acc[mt][nt][2] + b0)), 0.5f, 0.5f);
            float s11 = fmaf(tanh_fast(0.5f * (acc[mt][nt][3] + b1)), 0.5f, 0.5f);
            uint4 o0, o1;
            o0.x = x0.x; o0.y = __float_as_uint(s00);
            o0.z = x0.y; o0.w = __float_as_uint(s01);
            o1.x = x1.x; o1.y = __float_as_uint(s10);
            o1.z = x1.y; o1.w = __float_as_uint(s11);
            *reinterpret_cast<uint4*>(&C2[(size_t)row * 256 + col]) = o0;
            *reinterpret_cast<uint4*>(&C2[(size_t)(row + 8) * 256 + col]) = o1;
        }
    }
}

// ---------------------------------------------------------------------------
__global__ __launch_bounds__(256) void prep_w(const float* __restrict__ W2,
                                              uint32_t* __restrict__ W2p)
{
    int i = blockIdx.x * blockDim.x + threadIdx.x;
    W2p[i] = pack_hl(W2[i]);
}

// ---------------------------------------------------------------------------
// Recurrence: single uint2 {x_packed, sigma_f32} stream; ring depth 32.
// POUT: write packed u32 (layer0) else fp32 (layer1 -> d_out).
// ---------------------------------------------------------------------------
#define PD 32

template <bool POUT>
__global__ __launch_bounds__(128) void recur2(
    const uint2* __restrict__ X0,
    uint32_t* __restrict__ P0, float* __restrict__ F0, int yld0, int yoff0,
    const uint2* __restrict__ X1,
    uint32_t* __restrict__ P1, float* __restrict__ F1, int yld1, int yoff1)
{
    const int dir = blockIdx.y;
    const uint2* __restrict__ X = dir ? X1 : X0;
    uint32_t* __restrict__ Yp = dir ? P1 : P0;
    float*    __restrict__ Yf = dir ? F1 : F0;
    const int yld  = dir ? yld1  : yld0;
    const int yoff = dir ? yoff1 : yoff0;

    const int gg = blockIdx.x * blockDim.x + threadIdx.x;
    const int b = gg >> 8;
    const int j = gg & 255;

    const int t0 = dir ? (SEQ - 1) : 0;
    const ptrdiff_t xstep = dir ? -(ptrdiff_t)HID : (ptrdiff_t)HID;
    const ptrdiff_t ystep = dir ? -(ptrdiff_t)yld : (ptrdiff_t)yld;

    const uint2* xp = X + ((size_t)b * SEQ + t0) * HID + j;
    const size_t ybase = (size_t)b * SEQ * yld + (size_t)t0 * yld + yoff + j;
    uint32_t* ypp = POUT ? (Yp + ybase) : nullptr;
    float*    ypf = POUT ? nullptr : (Yf + ybase);

    uint2 xr[PD];
    #pragma unroll
    for (int d = 0; d < PD; d++)
        xr[d] = xp[(ptrdiff_t)d * xstep];
    const uint2* xq = xp + (ptrdiff_t)PD * xstep;

    float h = 0.f;
    #pragma unroll 1
    for (int blk = 0; blk < SEQ / PD - 1; blk++) {
        #pragma unroll
        for (int d = 0; d < PD; d++) {
            float xv = unpack_hl(xr[d].x);
            float a  = __uint_as_float(xr[d].y);
            float c  = fmaf(-a, xv, xv);
            float t  = fmaf(a, h, c);
            h = tanh_fast(xv * t);
            if (POUT) { *ypp = pack_hl(h); ypp += ystep; }
            else      { *ypf = h;          ypf += ystep; }
            xr[d] = *xq;
            xq += xstep;
        }
    }
    #pragma unroll
    for (int d = 0; d < PD; d++) {
        float xv = unpack_hl(xr[d].x);
        float a  = __uint_as_float(xr[d].y);
        float c  = fmaf(-a, xv, xv);
        float t  = fmaf(a, h, c);
        h = tanh_fast(xv * t);
        if (POUT) { *ypp = pack_hl(h); ypp += ystep; }
        else      { *ypf = h;          ypf += ystep; }
    }
}

// ---------------------------------------------------------------------------
__global__ __launch_bounds__(256) void copy_hout(
    const uint32_t* __restrict__ Ypl, const uint32_t* __restrict__ Ypr,
    const float* __restrict__ xx, float* __restrict__ hout)
{
    int gg = blockIdx.x * blockDim.x + threadIdx.x;
    int j = gg & 255;
    int b = (gg >> 8) & 31;
    int s = gg >> 13;
    float v;
    if      (s == 0) v = unpack_hl(Ypl[((size_t)b * SEQ + (SEQ - 1)) * HID + j]);
    else if (s == 1) v = unpack_hl(Ypr[((size_t)b * SEQ) * HID + j]);
    else if (s == 2) v = xx[((size_t)b * SEQ + (SEQ - 1)) * (2 * HID) + j];
    else             v = xx[((size_t)b * SEQ) * (2 * HID) + HID + j];
    hout[gg] = v;
}

// ---------------------------------------------------------------------------
extern "C" void kernel_launch(void* const* d_in, const int* in_sizes, int n_in,
                              void* d_out, int out_size)
{
    const float* x    = (const float*)d_in[0];
    const float* W_fc = (const float*)d_in[1];
    const float* b_fc = (const float*)d_in[2];
    // d_in[3] = W1, d_in[4] = b1 : dead (g1*x + (1-g1)*x == x)
    const float* W2   = (const float*)d_in[5];
    const float* b2   = (const float*)d_in[6];
    float* out = (float*)d_out;

    uint32_t *Pp, *Yp, *W2p;
    uint2 *C0, *C1;
    cudaGetSymbolAddress((void**)&Pp,  g_Pp);
    cudaGetSymbolAddress((void**)&Yp,  g_Yp);
    cudaGetSymbolAddress((void**)&C0,  g_C0);
    cudaGetSymbolAddress((void**)&C1,  g_C1);
    cudaGetSymbolAddress((void**)&W2p, g_W2p);

    uint32_t* Ypl = Yp;
    uint32_t* Ypr = Yp + (size_t)MROWS * HID;
    float* hout = out + (size_t)BSZ * SEQ * 2 * HID;

    // 0) pre-split W2 (both layers) into packed format
    prep_w<<<2 * HID * HID / 256, 256>>>(W2, W2p);

    // 1) fc projection -> packed P
    {
        dim3 grid(MROWS / 128, 2);
        gemm_fc<<<grid, 256>>>(x, W_fc, b_fc, Pp);
    }

    // 2) layer 0 gates (shared by both dirs) -> combined {x, sigma}
    {
        dim3 grid(MROWS / 128, 2);
        gemm_gate<<<grid, 256>>>(Pp, W2p, b2, C0);
    }

    // 3) layer 0 recurrence -> packed Y
    {
        dim3 grid(NLANE / 128, 2);
        recur2<true><<<grid, 128>>>(C0, Ypl, nullptr, HID, 0,
                                    C0, Ypr, nullptr, HID, 0);
    }

    // 4) layer 1 gates: one GEMM over [2*MROWS, 256] -> combined
    {
        dim3 grid(2 * MROWS / 128, 2);
        gemm_gate<<<grid, 256>>>(Yp, W2p + HID * HID, b2 + HID, C1);
    }

    // 5) layer 1 recurrence -> d_out fp32 (feature stride 512)
    {
        dim3 grid(NLANE / 128, 2);
        recur2<false><<<grid, 128>>>(C1, nullptr, out, 2 * HID, 0,
                                     C1 + (size_t)MROWS * HID, nullptr, out, 2 * HID, HID);
    }

    // 6) final hidden states
    copy_hout<<<BSZ * HID * 4 / 256, 256>>>(Ypl, Ypr, out, hout);
}

// round 14
// speedup vs baseline: 1.3505x; 1.0018x over previous
#include <cuda_runtime.h>
#include <cuda_bf16.h>
#include <cuda_fp16.h>
#include <cstdint>
#include <cstddef>

// Problem dims
#define BSZ  32
#define SEQ  2048
#define IND  512
#define HID  256
#define MROWS (BSZ * SEQ)          // 65536
#define NLANE (BSZ * HID)          // 8192 per direction

// ---------------- scratch (device globals; no allocs allowed) ---------------
// activations stored as separate bf16 hi/lo planes (hi+lo ~= fp32 value)
__device__ __nv_bfloat16 g_Ph[MROWS * HID];       // fc output hi
__device__ __nv_bfloat16 g_Pl[MROWS * HID];       // fc output lo
__device__ __nv_bfloat16 g_Yh[2 * MROWS * HID];   // layer0 out hi [ltr|rtl]
__device__ __nv_bfloat16 g_Yl[2 * MROWS * HID];   // layer0 out lo
__device__ __nv_bfloat16 g_W2h[2 * HID * HID];    // W2 hi (both layers)
__device__ __nv_bfloat16 g_W2l[2 * HID * HID];    // W2 lo
__device__ uint2 g_C0[MROWS * HID];               // layer0 recur input {x_packed, sigma}
__device__ uint2 g_C1[2 * MROWS * HID];           // layer1 recur input

__device__ __forceinline__ float tanh_fast(float x) {
    float y;
    asm("tanh.approx.f32 %0, %1;" : "=f"(y) : "f"(x));
    return y;
}

__device__ __forceinline__ uint32_t smem_u32(const void* p) {
    uint32_t a;
    asm("{ .reg .u64 t; cvta.to.shared.u64 t, %1; cvt.u32.u64 %0, t; }"
        : "=r"(a) : "l"(p));
    return a;
}

__device__ __forceinline__ uint32_t prmt(uint32_t a, uint32_t b, uint32_t sel) {
    uint32_t r;
    asm("prmt.b32 %0, %1, %2, %3;" : "=r"(r) : "r"(a), "r"(b), "r"(sel));
    return r;
}

__device__ __forceinline__ void split2(float a, float b, uint32_t& hi, uint32_t& lo) {
    __nv_bfloat16 ha = __float2bfloat16_rn(a);
    __nv_bfloat16 hb = __float2bfloat16_rn(b);
    float ra = a - __bfloat162float(ha);
    float rb = b - __bfloat162float(hb);
    __nv_bfloat162 hh; hh.x = ha; hh.y = hb;
    __nv_bfloat162 ll = __floats2bfloat162_rn(ra, rb);
    hi = *reinterpret_cast<uint32_t*>(&hh);
    lo = *reinterpret_cast<uint32_t*>(&ll);
}

__device__ __forceinline__ float unpack_hl(uint32_t p) {
    float hi = __uint_as_float(p & 0xFFFF0000u);
    float lo = __uint_as_float(p << 16);
    return hi + lo;
}

__device__ __forceinline__ void mma16816(
    float c[4], uint32_t a0, uint32_t a1, uint32_t a2, uint32_t a3,
    uint32_t b0, uint32_t b1)
{
    asm volatile(
        "mma.sync.aligned.m16n8k16.row.col.f32.bf16.bf16.f32 "
        "{%0,%1,%2,%3}, {%4,%5,%6,%7}, {%8,%9}, {%0,%1,%2,%3};"
        : "+f"(c[0]), "+f"(c[1]), "+f"(c[2]), "+f"(c[3])
        : "r"(a0), "r"(a1), "r"(a2), "r"(a3), "r"(b0), "r"(b1));
}

#define LDSM_X4(r0, r1, r2, r3, addr) \
    asm volatile("ldmatrix.sync.aligned.m8n8.x4.shared.b16 {%0,%1,%2,%3}, [%4];" \
        : "=r"(r0), "=r"(r1), "=r"(r2), "=r"(r3) : "r"(addr))

#define CP_ASYNC16(dst, src) \
    asm volatile("cp.async.cg.shared.global [%0], [%1], 16;" \
        :: "r"(dst), "l"(src))
#define CP_COMMIT()  asm volatile("cp.async.commit_group;" ::: "memory")
#define CP_WAIT1()   asm volatile("cp.async.wait_group 1;" ::: "memory")

#define SB 80          // smem row stride bytes (64B data + 16B pad)
#define OPB 10240      // one plane: 128 rows * SB
#define STAGEB 40960   // 4 planes
#define SMEM_GATE 81920 // 2 stages

// ===========================================================================
// GEMM compute core: BM=128, BN=128, BK=32; 8 warps (4Mx2N), warp tile 32x64.
// Planes at stage+0:Ah, +OPB:Al, +2OPB:Wh, +3OPB:Wl.
// ===========================================================================
__device__ __forceinline__ void gemm_compute(
    uint32_t stage, uint32_t aoff, uint32_t boff, int wm, int wn, float acc[2][8][4])
{
    #pragma unroll
    for (int pass = 0; pass < 3; pass++) {
        const uint32_t uAt = stage + ((pass == 1) ? OPB : 0);
        const uint32_t uWt = stage + ((pass == 2) ? 3 * OPB : 2 * OPB);
        const uint32_t aBase = uAt + (uint32_t)(wm * SB) + aoff;
        const uint32_t bBase = uWt + (uint32_t)(wn * SB) + boff;
        #pragma unroll
        for (int ks = 0; ks < 2; ks++) {
            const uint32_t ko = ks * 32;
            uint32_t bfr[8][2];
            #pragma unroll
            for (int p = 0; p < 4; p++) {
                LDSM_X4(bfr[2*p][0], bfr[2*p][1], bfr[2*p+1][0], bfr[2*p+1][1],
                        bBase + (uint32_t)(p * 16 * SB) + ko);
            }
            #pragma unroll
            for (int mt = 0; mt < 2; mt++) {
                uint32_t a0, a1, a2, a3;
                LDSM_X4(a0, a1, a2, a3, aBase + (uint32_t)(mt * 16 * SB) + ko);
                #pragma unroll
                for (int nt = 0; nt < 8; nt++)
                    mma16816(acc[mt][nt], a0, a1, a2, a3, bfr[nt][0], bfr[nt][1]);
            }
        }
    }
}

// ---------------------------------------------------------------------------
// fc GEMM: fp32 inputs (x, W_fc), split in loader (single-buffered, as R11).
// Epilogue writes bf16 hi/lo planes.
// ---------------------------------------------------------------------------
__global__ __launch_bounds__(256, 2) void gemm_fc(
    const float* __restrict__ A, const float* __restrict__ W,
    const float* __restrict__ bias,
    __nv_bfloat16* __restrict__ Ch, __nv_bfloat16* __restrict__ Cl)
{
    __shared__ __align__(16) char sm[STAGEB];

    const int tid  = threadIdx.x;
    const int lane = tid & 31;
    const int warp = tid >> 5;
    const int wm = (warp & 3) * 32, wn = (warp >> 2) * 64;
    const int r = lane >> 2, q = lane & 3;
    const uint32_t uS = smem_u32(sm);
    const uint32_t aoff = (uint32_t)((lane & 15) * SB + ((lane >> 4) << 4));
    const uint32_t boff = (uint32_t)(((lane & 7) + (lane >> 4) * 8) * SB + ((lane & 8) << 1));

    const int bm  = blockIdx.x * 128;
    const int bnG = blockIdx.y * 128;
    const int K = IND;

    float acc[2][8][4];
    #pragma unroll
    for (int mt = 0; mt < 2; mt++)
        #pragma unroll
        for (int nt = 0; nt < 8; nt++)
            #pragma unroll
            for (int e = 0; e < 4; e++) acc[mt][nt][e] = 0.f;

    for (int c = 0; c < (K >> 5); c++) {
        const int k0 = c << 5;
        #pragma unroll
        for (int i = 0; i < 4; i++) {
            int idx = i * 256 + tid;
            int row = idx >> 3;
            int c4  = (idx & 7) * 4;
            float4 va = *reinterpret_cast<const float4*>(
                &A[(size_t)(bm + row) * K + k0 + c4]);
            float4 vw = *reinterpret_cast<const float4*>(
                &W[(size_t)(bnG + row) * K + k0 + c4]);
            uint2 ahi, alo, whi, wlo;
            split2(va.x, va.y, ahi.x, alo.x);
            split2(va.z, va.w, ahi.y, alo.y);
            split2(vw.x, vw.y, whi.x, wlo.x);
            split2(vw.z, vw.w, whi.y, wlo.y);
            int off = row * SB + c4 * 2;
            *reinterpret_cast<uint2*>(sm + off) = ahi;
            *reinterpret_cast<uint2*>(sm + OPB + off) = alo;
            *reinterpret_cast<uint2*>(sm + 2*OPB + off) = whi;
            *reinterpret_cast<uint2*>(sm + 3*OPB + off) = wlo;
        }
        __syncthreads();
        gemm_compute(uS, aoff, boff, wm, wn, acc);
        __syncthreads();
    }

    #pragma unroll
    for (int mt = 0; mt < 2; mt++) {
        const int row = bm + wm + mt * 16 + r;
        #pragma unroll
        for (int nt = 0; nt < 8; nt++) {
            const int col = bnG + wn + nt * 8 + q * 2;
            float b0 = bias[col], b1 = bias[col + 1];
            float v00 = acc[mt][nt][0] + b0, v01 = acc[mt][nt][1] + b1;
            float v10 = acc[mt][nt][2] + b0, v11 = acc[mt][nt][3] + b1;
            __nv_bfloat162 h0, l0, h1, l1;
            h0.x = __float2bfloat16_rn(v00); h0.y = __float2bfloat16_rn(v01);
            l0.x = __float2bfloat16_rn(v00 - __bfloat162float(h0.x));
            l0.y = __float2bfloat16_rn(v01 - __bfloat162float(h0.y));
            h1.x = __float2bfloat16_rn(v10); h1.y = __float2bfloat16_rn(v11);
            l1.x = __float2bfloat16_rn(v10 - __bfloat162float(h1.x));
            l1.y = __float2bfloat16_rn(v11 - __bfloat162float(h1.y));
            *reinterpret_cast<__nv_bfloat162*>(&Ch[(size_t)row * 256 + col]) = h0;
            *reinterpret_cast<__nv_bfloat162*>(&Cl[(size_t)row * 256 + col]) = l0;
            *reinterpret_cast<__nv_bfloat162*>(&Ch[(size_t)(row + 8) * 256 + col]) = h1;
            *reinterpret_cast<__nv_bfloat162*>(&Cl[(size_t)(row + 8) * 256 + col]) = l1;
        }
    }
}

// ---------------------------------------------------------------------------
// Gate GEMM: pre-split bf16 planes, cp.async 2-stage pipeline, K=256.
// Epilogue emits combined uint2 {x_packed, sigma_fp32}.
// ---------------------------------------------------------------------------
__global__ __launch_bounds__(256, 2) void gemm_gate(
    const __nv_bfloat16* __restrict__ Ah, const __nv_bfloat16* __restrict__ Al,
    const __nv_bfloat16* __restrict__ Wh, const __nv_bfloat16* __restrict__ Wl,
    const float* __restrict__ bias, uint2* __restrict__ C2)
{
    extern __shared__ __align__(16) char sm[];
    const int tid  = threadIdx.x;
    const int lane = tid & 31;
    const int warp = tid >> 5;
    const int wm = (warp & 3) * 32, wn = (warp >> 2) * 64;
    const int r = lane >> 2, q = lane & 3;
    const uint32_t uS = smem_u32(sm);
    const uint32_t aoff = (uint32_t)((lane & 15) * SB + ((lane >> 4) << 4));
    const uint32_t boff = (uint32_t)(((lane & 7) + (lane >> 4) * 8) * SB + ((lane & 8) << 1));

    const int bm  = blockIdx.x * 128;
    const int bnG = blockIdx.y * 128;
    const int K = HID;   // 256

    // loader mapping: 8 x 16B per thread per stage (2048 chunks / 256 threads)
    // chunk ci: plane = ci>>9, row = (ci>>2)&127, seg = ci&3
    const __nv_bfloat16* planes[4] = {
        Ah + (size_t)bm * K, Al + (size_t)bm * K,
        Wh + (size_t)bnG * K, Wl + (size_t)bnG * K };

    float acc[2][8][4];
    #pragma unroll
    for (int mt = 0; mt < 2; mt++)
        #pragma unroll
        for (int nt = 0; nt < 8; nt++)
            #pragma unroll
            for (int e = 0; e < 4; e++) acc[mt][nt][e] = 0.f;

    const int nch = K >> 5;   // 8
    // issue a stage's copies: chunk c -> buffer (c&1)
    auto issue = [&](int c) {
        const int k0 = c << 5;
        const uint32_t sbase = uS + (uint32_t)((c & 1) * STAGEB);
        #pragma unroll
        for (int it = 0; it < 8; it++) {
            int ci = it * 256 + tid;
            int pl = ci >> 9;
            int row = (ci >> 2) & 127;
            int seg = ci & 3;
            const __nv_bfloat16* src = planes[pl] + (size_t)row * K + k0 + seg * 8;
            uint32_t dst = sbase + (uint32_t)(pl * OPB + row * SB + seg * 16);
            CP_ASYNC16(dst, src);
        }
        CP_COMMIT();
    };

    issue(0);
    issue(1);

    for (int c = 0; c < nch; c++) {
        CP_WAIT1();
        __syncthreads();
        gemm_compute(uS + (uint32_t)((c & 1) * STAGEB), aoff, boff, wm, wn, acc);
        __syncthreads();
        if (c + 2 < nch) issue(c + 2);
        else CP_COMMIT();   // keep group accounting uniform
    }

    // epilogue: sigma fp32 + x rebuild from hi/lo planes -> {x_packed, sigma}
    #pragma unroll
    for (int mt = 0; mt < 2; mt++) {
        const int row = bm + wm + mt * 16 + r;
        #pragma unroll
        for (int nt = 0; nt < 8; nt++) {
            const int col = bnG + wn + nt * 8 + q * 2;
            float b0 = bias[col], b1 = bias[col + 1];
            uint32_t h0 = *reinterpret_cast<const uint32_t*>(&Ah[(size_t)row * 256 + col]);
            uint32_t l0 = *reinterpret_cast<const uint32_t*>(&Al[(size_t)row * 256 + col]);
            uint32_t h1 = *reinterpret_cast<const uint32_t*>(&Ah[(size_t)(row + 8) * 256 + col]);
            uint32_t l1 = *reinterpret_cast<const uint32_t*>(&Al[(size_t)(row + 8) * 256 + col]);
            float s00 = fmaf(tanh_fast(0.5f * (acc[mt][nt][0] + b0)), 0.5f, 0.5f);
            float s01 = fmaf(tanh_fast(0.5f * (acc[mt][nt][1] + b1)), 0.5f, 0.5f);
            float s10 = fmaf(tanh_fast(0.5f * (acc[mt][nt][2] + b0)), 0.5f, 0.5f);
            float s11 = fmaf(tanh_fast(0.5f * (acc[mt][nt][3] + b1)), 0.5f, 0.5f);
            uint4 o0, o1;
            o0.x = prmt(l0, h0, 0x5410); o0.y = __float_as_uint(s00);
            o0.z = prmt(l0, h0, 0x7632); o0.w = __float_as_uint(s01);
            o1.x = prmt(l1, h1, 0x5410); o1.y = __float_as_uint(s10);
            o1.z = prmt(l1, h1, 0x7632); o1.w = __float_as_uint(s11);
            *reinterpret_cast<uint4*>(&C2[(size_t)row * 256 + col]) = o0;
            *reinterpret_cast<uint4*>(&C2[(size_t)(row + 8) * 256 + col]) = o1;
        }
    }
}

// ---------------------------------------------------------------------------
__global__ __launch_bounds__(256) void prep_w(const float* __restrict__ W2,
    __nv_bfloat16* __restrict__ W2h, __nv_bfloat16* __restrict__ W2l)
{
    int i = blockIdx.x * blockDim.x + threadIdx.x;
    float v = W2[i];
    __nv_bfloat16 h = __float2bfloat16_rn(v);
    W2h[i] = h;
    W2l[i] = __float2bfloat16_rn(v - __bfloat162float(h));
}

// ---------------------------------------------------------------------------
// Recurrence: single uint2 {x_packed, sigma_f32} stream; ring depth 32.
// POUT: write bf16 hi/lo planes (layer0) else fp32 (layer1 -> d_out).
// ---------------------------------------------------------------------------
#define PD 32

template <bool POUT>
__global__ __launch_bounds__(128) void recur2(
    const uint2* __restrict__ X0,
    __nv_bfloat16* __restrict__ H0, __nv_bfloat16* __restrict__ L0buf,
    float* __restrict__ F0, int yld0, int yoff0,
    const uint2* __restrict__ X1,
    __nv_bfloat16* __restrict__ H1, __nv_bfloat16* __restrict__ L1buf,
    float* __restrict__ F1, int yld1, int yoff1)
{
    const int dir = blockIdx.y;
    const uint2* __restrict__ X = dir ? X1 : X0;
    __nv_bfloat16* __restrict__ Yh = dir ? H1 : H0;
    __nv_bfloat16* __restrict__ Yl = dir ? L1buf : L0buf;
    float* __restrict__ Yf = dir ? F1 : F0;
    const int yld  = dir ? yld1  : yld0;
    const int yoff = dir ? yoff1 : yoff0;

    const int gg = blockIdx.x * blockDim.x + threadIdx.x;
    const int b = gg >> 8;
    const int j = gg & 255;

    const int t0 = dir ? (SEQ - 1) : 0;
    const ptrdiff_t xstep = dir ? -(ptrdiff_t)HID : (ptrdiff_t)HID;
    const ptrdiff_t ystep = dir ? -(ptrdiff_t)yld : (ptrdiff_t)yld;

    const uint2* xp = X + ((size_t)b * SEQ + t0) * HID + j;
    const size_t ybase = (size_t)b * SEQ * yld + (size_t)t0 * yld + yoff + j;
    __nv_bfloat16* yph = POUT ? (Yh + ybase) : nullptr;
    __nv_bfloat16* ypl = POUT ? (Yl + ybase) : nullptr;
    float*         ypf = POUT ? nullptr : (Yf + ybase);

    uint2 xr[PD];
    #pragma unroll
    for (int d = 0; d < PD; d++)
        xr[d] = xp[(ptrdiff_t)d * xstep];
    const uint2* xq = xp + (ptrdiff_t)PD * xstep;

    float h = 0.f;
    #pragma unroll 1
    for (int blk = 0; blk < SEQ / PD - 1; blk++) {
        #pragma unroll
        for (int d = 0; d < PD; d++) {
            float xv = unpack_hl(xr[d].x);
            float a  = __uint_as_float(xr[d].y);
            float c  = fmaf(-a, xv, xv);
            float t  = fmaf(a, h, c);
            h = tanh_fast(xv * t);
            if (POUT) {
                __nv_bfloat16 hb = __float2bfloat16_rn(h);
                *yph = hb;
                *ypl = __float2bfloat16_rn(h - __bfloat162float(hb));
                yph += ystep; ypl += ystep;
            } else {
                *ypf = h; ypf += ystep;
            }
            xr[d] = *xq;
            xq += xstep;
        }
    }
    #pragma unroll
    for (int d = 0; d < PD; d++) {
        float xv = unpack_hl(xr[d].x);
        float a  = __uint_as_float(xr[d].y);
        float c  = fmaf(-a, xv, xv);
        float t  = fmaf(a, h, c);
        h = tanh_fast(xv * t);
        if (POUT) {
            __nv_bfloat16 hb = __float2bfloat16_rn(h);
            *yph = hb;
            *ypl = __float2bfloat16_rn(h - __bfloat162float(hb));
            yph += ystep; ypl += ystep;
        } else {
            *ypf = h; ypf += ystep;
        }
    }
}

// ---------------------------------------------------------------------------
__global__ __launch_bounds__(256) void copy_hout(
    const __nv_bfloat16* __restrict__ Yh, const __nv_bfloat16* __restrict__ Yl,
    const float* __restrict__ xx, float* __restrict__ hout)
{
    int gg = blockIdx.x * blockDim.x + threadIdx.x;
    int j = gg & 255;
    int b = (gg >> 8) & 31;
    int s = gg >> 13;
    float v;
    if (s == 0) {
        size_t i = ((size_t)b * SEQ + (SEQ - 1)) * HID + j;
        v = __bfloat162float(Yh[i]) + __bfloat162float(Yl[i]);
    } else if (s == 1) {
        size_t i = (size_t)MROWS * HID + ((size_t)b * SEQ) * HID + j;
        v = __bfloat162float(Yh[i]) + __bfloat162float(Yl[i]);
    } else if (s == 2) {
        v = xx[((size_t)b * SEQ + (SEQ - 1)) * (2 * HID) + j];
    } else {
        v = xx[((size_t)b * SEQ) * (2 * HID) + HID + j];
    }
    hout[gg] = v;
}

// ---------------------------------------------------------------------------
extern "C" void kernel_launch(void* const* d_in, const int* in_sizes, int n_in,
                              void* d_out, int out_size)
{
    const float* x    = (const float*)d_in[0];
    const float* W_fc = (const float*)d_in[1];
    const float* b_fc = (const float*)d_in[2];
    // d_in[3] = W1, d_in[4] = b1 : dead (g1*x + (1-g1)*x == x)
    const float* W2   = (const float*)d_in[5];
    const float* b2   = (const float*)d_in[6];
    float* out = (float*)d_out;

    __nv_bfloat16 *Ph, *Pl, *Yh, *Yl, *W2h, *W2l;
    uint2 *C0, *C1;
    cudaGetSymbolAddress((void**)&Ph,  g_Ph);
    cudaGetSymbolAddress((void**)&Pl,  g_Pl);
    cudaGetSymbolAddress((void**)&Yh,  g_Yh);
    cudaGetSymbolAddress((void**)&Yl,  g_Yl);
    cudaGetSymbolAddress((void**)&W2h, g_W2h);
    cudaGetSymbolAddress((void**)&W2l, g_W2l);
    cudaGetSymbolAddress((void**)&C0,  g_C0);
    cudaGetSymbolAddress((void**)&C1,  g_C1);

    float* hout = out + (size_t)BSZ * SEQ * 2 * HID;

    cudaFuncSetAttribute(gemm_gate, cudaFuncAttributeMaxDynamicSharedMemorySize, SMEM_GATE);

    // 0) pre-split W2 (both layers) into hi/lo planes
    prep_w<<<2 * HID * HID / 256, 256>>>(W2, W2h, W2l);

    // 1) fc projection -> P hi/lo planes
    {
        dim3 grid(MROWS / 128, 2);
        gemm_fc<<<grid, 256>>>(x, W_fc, b_fc, Ph, Pl);
    }

    // 2) layer 0 gates (shared by both dirs) -> combined {x, sigma}
    {
        dim3 grid(MROWS / 128, 2);
        gemm_gate<<<grid, 256, SMEM_GATE>>>(Ph, Pl, W2h, W2l, b2, C0);
    }

    // 3) layer 0 recurrence -> Y hi/lo planes
    {
        dim3 grid(NLANE / 128, 2);
        recur2<true><<<grid, 128>>>(
            C0, Yh, Yl, nullptr, HID, 0,
            C0, Yh + (size_t)MROWS * HID, Yl + (size_t)MROWS * HID, nullptr, HID, 0);
    }

    // 4) layer 1 gates: one GEMM over [2*MROWS, 256]
    {
        dim3 grid(2 * MROWS / 128, 2);
        gemm_gate<<<grid, 256, SMEM_GATE>>>(Yh, Yl, W2h + HID * HID, W2l + HID * HID,
                                            b2 + HID, C1);
    }

    // 5) layer 1 recurrence -> d_out fp32 (feature stride 512)
    {
        dim3 grid(NLANE / 128, 2);
        recur2<false><<<grid, 128>>>(
            C1, nullptr, nullptr, out, 2 * HID, 0,
            C1 + (size_t)MROWS * HID, nullptr, nullptr, out, 2 * HID, HID);
    }

    // 6) final hidden states
    copy_hout<<<BSZ * HID * 4 / 256, 256>>>(Yh, Yl, out, hout);
}